// round 1
// baseline (speedup 1.0000x reference)
#include <cuda_runtime.h>
#include <math.h>

#define MAXN 50000
#define MAXE 800000

// ---------------- scratch (static device globals; no allocs allowed) ----------------
__device__ int   g_cnt[MAXN];
__device__ int   g_off[MAXN + 1];
__device__ int   g_cursor[MAXN];
__device__ int   g_bsum[64];
__device__ float g_dis[MAXN];
__device__ int   g_csr_row[MAXE];
__device__ float g_xws[(size_t)MAXN * 64];  // (x@W1)*dis
__device__ float g_h  [(size_t)MAXN * 64];  // relu(layer1)
__device__ float g_hws[(size_t)MAXN * 64];  // (h@W2)*dis
__device__ float g_z  [(size_t)MAXN * 64];  // layer2 out

// ---------------- CSR build ----------------
__global__ void k_zero_cnt(int n) {
    int i = blockIdx.x * blockDim.x + threadIdx.x;
    if (i < n) g_cnt[i] = 0;
}

__global__ void k_count(const int* __restrict__ ei, int nE) {
    int e = blockIdx.x * blockDim.x + threadIdx.x;
    if (e < nE) atomicAdd(&g_cnt[ei[nE + e]], 1);  // col = target
}

__global__ void k_scanA(int n) {
    __shared__ int s[1024];
    int t = threadIdx.x;
    int i = blockIdx.x * 1024 + t;
    int v = (i < n) ? g_cnt[i] : 0;
    s[t] = v;
    __syncthreads();
#pragma unroll
    for (int d = 1; d < 1024; d <<= 1) {
        int x = (t >= d) ? s[t - d] : 0;
        __syncthreads();
        s[t] += x;
        __syncthreads();
    }
    if (i < n) g_off[i] = s[t] - v;     // exclusive within block
    if (t == 1023) g_bsum[blockIdx.x] = s[1023];
}

__global__ void k_scanB(int nb, int n) {
    if (threadIdx.x == 0 && blockIdx.x == 0) {
        int c = 0;
        for (int b = 0; b < nb; b++) {
            int t = g_bsum[b];
            g_bsum[b] = c;
            c += t;
        }
        g_off[n] = c;
    }
}

__global__ void k_scanC(int n) {
    int i = blockIdx.x * blockDim.x + threadIdx.x;
    if (i < n) {
        int o = g_off[i] + g_bsum[i >> 10];
        g_off[i] = o;
        g_cursor[i] = o;
        g_dis[i] = rsqrtf((float)(g_cnt[i] + 1));   // deg = in-degree + self-loop
    }
}

__global__ void k_scatter(const int* __restrict__ ei, int nE) {
    int e = blockIdx.x * blockDim.x + threadIdx.x;
    if (e < nE) {
        int row = ei[e];
        int col = ei[nE + e];
        int p = atomicAdd(&g_cursor[col], 1);
        g_csr_row[p] = row;
    }
}

// ---------------- GEMM: out[r][c] = (A[r][:] @ W[:][c]) * dis[r] ----------------
// A: [n, K] row-major, W: [K, 64] row-major, out: [n, 64].
// Block = 256 threads, tile 64 rows x 64 cols, thread tile 4x4, K-chunks of 64.
template <int K>
__global__ void k_gemm_scaled(const float* __restrict__ A, const float* __restrict__ W,
                              float* __restrict__ out, int n) {
    __shared__ float xs[64][64];   // rows x k
    __shared__ float ws[64][64];   // k x cols
    int t = threadIdx.x;
    int tx = t & 15;      // col group (x4)
    int ty = t >> 4;      // row group (x4)
    int row0 = blockIdx.x * 64;

    float acc[4][4] = {};

    for (int kc = 0; kc < K; kc += 64) {
#pragma unroll
        for (int it = 0; it < 4; it++) {
            int v = it * 256 + t;        // 0..1023 float4 slots
            int r = v >> 4;              // 0..63
            int q = v & 15;              // 0..15 (x4 floats)
            int gr = min(row0 + r, n - 1);
            float4 xv = *(const float4*)(A + (size_t)gr * K + kc + q * 4);
            *(float4*)&xs[r][q * 4] = xv;
            float4 wv = *(const float4*)(W + (size_t)(kc + r) * 64 + q * 4);
            *(float4*)&ws[r][q * 4] = wv;
        }
        __syncthreads();

#pragma unroll
        for (int k = 0; k < 64; k++) {
            float4 wf = *(const float4*)&ws[k][tx * 4];
            float xf[4];
#pragma unroll
            for (int i = 0; i < 4; i++) xf[i] = xs[ty * 4 + i][k];
#pragma unroll
            for (int i = 0; i < 4; i++) {
                acc[i][0] = fmaf(xf[i], wf.x, acc[i][0]);
                acc[i][1] = fmaf(xf[i], wf.y, acc[i][1]);
                acc[i][2] = fmaf(xf[i], wf.z, acc[i][2]);
                acc[i][3] = fmaf(xf[i], wf.w, acc[i][3]);
            }
        }
        __syncthreads();
    }

#pragma unroll
    for (int i = 0; i < 4; i++) {
        int r = row0 + ty * 4 + i;
        if (r < n) {
            float d = g_dis[r];
            float4 o;
            o.x = acc[i][0] * d;
            o.y = acc[i][1] * d;
            o.z = acc[i][2] * d;
            o.w = acc[i][3] * d;
            *(float4*)(out + (size_t)r * 64 + tx * 4) = o;
        }
    }
}

// ---------------- Aggregation: out[i] = act(dis[i]*(sum_in in[row] + in[i]) + b) ----------------
// warp per node, each lane owns 2 channels (float2).
__global__ void k_aggregate(const float* __restrict__ in, float* __restrict__ out,
                            const float* __restrict__ bias, int n, int relu) {
    int node = blockIdx.x * 8 + (threadIdx.x >> 5);
    int lane = threadIdx.x & 31;
    if (node >= n) return;
    const float2* inp = (const float2*)in;
    float2 acc = inp[(size_t)node * 32 + lane];   // self-loop term (already *dis[row])
    int s = g_off[node], e = g_off[node + 1];
    for (int base = s; base < e; base += 32) {
        int idx = base + lane;
        int rr = (idx < e) ? g_csr_row[idx] : 0;
        int cnt = min(32, e - base);
        for (int j = 0; j < cnt; j++) {
            int row = __shfl_sync(0xffffffffu, rr, j);
            float2 v = inp[(size_t)row * 32 + lane];
            acc.x += v.x;
            acc.y += v.y;
        }
    }
    float d = g_dis[node];
    float2 bv = ((const float2*)bias)[lane];
    float ox = fmaf(d, acc.x, bv.x);
    float oy = fmaf(d, acc.y, bv.y);
    if (relu) { ox = fmaxf(ox, 0.f); oy = fmaxf(oy, 0.f); }
    float2 o; o.x = ox; o.y = oy;
    ((float2*)out)[(size_t)node * 32 + lane] = o;
}

// ---------------- Decode: out[e] = dot(z[src], z[dst]) ----------------
__global__ void k_decode(const int* __restrict__ eli, const float* __restrict__ z,
                         float* __restrict__ out, int nL) {
    int w = blockIdx.x * 8 + (threadIdx.x >> 5);
    int lane = threadIdx.x & 31;
    if (w >= nL) return;
    int s = eli[w];
    int d = eli[nL + w];
    const float2* z2 = (const float2*)z;
    float2 a = z2[(size_t)s * 32 + lane];
    float2 b = z2[(size_t)d * 32 + lane];
    float p = a.x * b.x + a.y * b.y;
#pragma unroll
    for (int o = 16; o > 0; o >>= 1) p += __shfl_down_sync(0xffffffffu, p, o);
    if (lane == 0) out[w] = p;
}

// ---------------- launch ----------------
extern "C" void kernel_launch(void* const* d_in, const int* in_sizes, int n_in,
                              void* d_out, int out_size) {
    const float* x   = (const float*)d_in[0];
    const int*   ei  = (const int*)  d_in[1];
    const int*   eli = (const int*)  d_in[2];
    const float* W1  = (const float*)d_in[3];
    const float* b1  = (const float*)d_in[4];
    const float* W2  = (const float*)d_in[5];
    const float* b2  = (const float*)d_in[6];
    float* out = (float*)d_out;

    int n  = in_sizes[0] / 256;
    int nE = in_sizes[1] / 2;
    int nL = in_sizes[2] / 2;

    // device-global scratch addresses (host-side symbol lookup; no allocation)
    void *p_xws, *p_h, *p_hws, *p_z;
    cudaGetSymbolAddress(&p_xws, g_xws);
    cudaGetSymbolAddress(&p_h,   g_h);
    cudaGetSymbolAddress(&p_hws, g_hws);
    cudaGetSymbolAddress(&p_z,   g_z);

    // CSR build (reused by both layers)
    k_zero_cnt<<<(n + 255) / 256, 256>>>(n);
    k_count<<<(nE + 255) / 256, 256>>>(ei, nE);
    int nb = (n + 1023) / 1024;
    k_scanA<<<nb, 1024>>>(n);
    k_scanB<<<1, 32>>>(nb, n);
    k_scanC<<<(n + 255) / 256, 256>>>(n);
    k_scatter<<<(nE + 255) / 256, 256>>>(ei, nE);

    int gb = (n + 63) / 64;
    // layer 1
    k_gemm_scaled<256><<<gb, 256>>>(x, W1, (float*)p_xws, n);
    k_aggregate<<<(n + 7) / 8, 256>>>((const float*)p_xws, (float*)p_h, b1, n, 1);
    // layer 2
    k_gemm_scaled<64><<<gb, 256>>>((const float*)p_h, W2, (float*)p_hws, n);
    k_aggregate<<<(n + 7) / 8, 256>>>((const float*)p_hws, (float*)p_z, b2, n, 0);
    // decode
    k_decode<<<(nL + 7) / 8, 256>>>(eli, (const float*)p_z, out, nL);
}